// round 1
// baseline (speedup 1.0000x reference)
#include <cuda_runtime.h>

#define N_NODES 200000
#define N_EDGES 1600000
#define F_IN    32
#define HDIM    24

// Scratch (allocation-free: device globals)
__device__ float g_x[N_NODES * HDIM];     // transformed features (layer input to scatter)
__device__ float g_agg[N_NODES * HDIM];   // scatter-add accumulator
__device__ int   g_deg_out[N_NODES];
__device__ int   g_deg_in[N_NODES];
__device__ float g_norm_src[N_NODES];
__device__ float g_norm_dst[N_NODES];

// ---------------------------------------------------------------------------
__global__ void k_zero() {
    int stride = gridDim.x * blockDim.x;
    int tid = blockIdx.x * blockDim.x + threadIdx.x;
    for (int i = tid; i < N_NODES * HDIM; i += stride) g_agg[i] = 0.0f;
    for (int i = tid; i < N_NODES; i += stride) {
        g_deg_out[i] = 0;
        g_deg_in[i]  = 0;
    }
}

__global__ void k_count(const int* __restrict__ src, const int* __restrict__ dst) {
    int e = blockIdx.x * blockDim.x + threadIdx.x;
    if (e < N_EDGES) {
        atomicAdd(&g_deg_out[__ldg(src + e)], 1);
        atomicAdd(&g_deg_in [__ldg(dst + e)], 1);
    }
}

__global__ void k_norm() {
    int n = blockIdx.x * blockDim.x + threadIdx.x;
    if (n < N_NODES) {
        g_norm_src[n] = rsqrtf(fmaxf((float)g_deg_out[n], 1.0f));
        g_norm_dst[n] = rsqrtf(fmaxf((float)g_deg_in [n], 1.0f));
    }
}

// x = (features * norm_src) @ W1, one thread per node
__global__ void k_transform1(const float* __restrict__ feats,
                             const float* __restrict__ W1) {
    __shared__ float sW[F_IN * HDIM];
    for (int i = threadIdx.x; i < F_IN * HDIM; i += blockDim.x) sW[i] = W1[i];
    __syncthreads();

    int n = blockIdx.x * blockDim.x + threadIdx.x;
    if (n >= N_NODES) return;

    float ns = g_norm_src[n];
    float acc[HDIM];
#pragma unroll
    for (int j = 0; j < HDIM; j++) acc[j] = 0.0f;

    const float4* frow = reinterpret_cast<const float4*>(feats + (size_t)n * F_IN);
#pragma unroll
    for (int k4 = 0; k4 < F_IN / 4; k4++) {
        float4 f = __ldg(frow + k4);
        float fv[4] = {f.x * ns, f.y * ns, f.z * ns, f.w * ns};
#pragma unroll
        for (int q = 0; q < 4; q++) {
            int k = k4 * 4 + q;
#pragma unroll
            for (int j = 0; j < HDIM; j++) acc[j] = fmaf(fv[q], sW[k * HDIM + j], acc[j]);
        }
    }

    float4* orow = reinterpret_cast<float4*>(g_x + (size_t)n * HDIM);
#pragma unroll
    for (int j4 = 0; j4 < HDIM / 4; j4++)
        orow[j4] = make_float4(acc[4*j4], acc[4*j4+1], acc[4*j4+2], acc[4*j4+3]);
}

// agg[dst] += x[src], vectorized red.global.add.v4.f32 (6 work items per edge)
__global__ void k_scatter(const int* __restrict__ src, const int* __restrict__ dst) {
    unsigned tid = blockIdx.x * blockDim.x + threadIdx.x;
    if (tid >= (unsigned)N_EDGES * 6u) return;
    unsigned e = tid / 6u;
    unsigned j = tid - e * 6u;
    int s = __ldg(src + e);
    int d = __ldg(dst + e);
    float4 v = __ldg(reinterpret_cast<const float4*>(g_x) + ((unsigned)s * 6u + j));
    float* p = g_agg + ((unsigned)d * 6u + j) * 4u;
    asm volatile("red.global.add.v4.f32 [%0], {%1,%2,%3,%4};"
                 :: "l"(p), "f"(v.x), "f"(v.y), "f"(v.z), "f"(v.w)
                 : "memory");
}

// h = relu(agg*norm_dst + b1); x = (h*norm_src) @ W2; agg = 0 (fused re-zero)
__global__ void k_mid(const float* __restrict__ W2, const float* __restrict__ b1) {
    __shared__ float sW[HDIM * HDIM];
    __shared__ float sb[HDIM];
    for (int i = threadIdx.x; i < HDIM * HDIM; i += blockDim.x) sW[i] = W2[i];
    if (threadIdx.x < HDIM) sb[threadIdx.x] = b1[threadIdx.x];
    __syncthreads();

    int n = blockIdx.x * blockDim.x + threadIdx.x;
    if (n >= N_NODES) return;

    float nd = g_norm_dst[n];
    float ns = g_norm_src[n];

    float4* arow = reinterpret_cast<float4*>(g_agg + (size_t)n * HDIM);
    float h[HDIM];
#pragma unroll
    for (int j4 = 0; j4 < HDIM / 4; j4++) {
        float4 a = arow[j4];
        h[4*j4+0] = fmaxf(fmaf(a.x, nd, sb[4*j4+0]), 0.0f) * ns;
        h[4*j4+1] = fmaxf(fmaf(a.y, nd, sb[4*j4+1]), 0.0f) * ns;
        h[4*j4+2] = fmaxf(fmaf(a.z, nd, sb[4*j4+2]), 0.0f) * ns;
        h[4*j4+3] = fmaxf(fmaf(a.w, nd, sb[4*j4+3]), 0.0f) * ns;
        arow[j4] = make_float4(0.f, 0.f, 0.f, 0.f);   // re-zero for layer 2
    }

    float acc[HDIM];
#pragma unroll
    for (int j = 0; j < HDIM; j++) acc[j] = 0.0f;
#pragma unroll
    for (int k = 0; k < HDIM; k++) {
#pragma unroll
        for (int j = 0; j < HDIM; j++) acc[j] = fmaf(h[k], sW[k * HDIM + j], acc[j]);
    }

    float4* orow = reinterpret_cast<float4*>(g_x + (size_t)n * HDIM);
#pragma unroll
    for (int j4 = 0; j4 < HDIM / 4; j4++)
        orow[j4] = make_float4(acc[4*j4], acc[4*j4+1], acc[4*j4+2], acc[4*j4+3]);
}

// h2 = relu(agg*norm_dst + b2); out[g] = sum_{k,j} h2[4g+k][j]*Wd[k*24+j] + bd
// one thread per node; 4-lane butterfly reduce; lane k==0 writes.
__global__ void k_final(const float* __restrict__ b2, const float* __restrict__ Wd,
                        const float* __restrict__ bd, float* __restrict__ out) {
    __shared__ float sWd[4 * HDIM];
    __shared__ float sb[HDIM];
    for (int i = threadIdx.x; i < 4 * HDIM; i += blockDim.x) sWd[i] = Wd[i];
    if (threadIdx.x < HDIM) sb[threadIdx.x] = b2[threadIdx.x];
    __syncthreads();

    int n = blockIdx.x * blockDim.x + threadIdx.x;
    if (n >= N_NODES) return;

    int k = n & 3;
    float nd = g_norm_dst[n];
    const float4* arow = reinterpret_cast<const float4*>(g_agg + (size_t)n * HDIM);
    const float* wrow = sWd + k * HDIM;

    float partial = 0.0f;
#pragma unroll
    for (int j4 = 0; j4 < HDIM / 4; j4++) {
        float4 a = arow[j4];
        partial = fmaf(fmaxf(fmaf(a.x, nd, sb[4*j4+0]), 0.f), wrow[4*j4+0], partial);
        partial = fmaf(fmaxf(fmaf(a.y, nd, sb[4*j4+1]), 0.f), wrow[4*j4+1], partial);
        partial = fmaf(fmaxf(fmaf(a.z, nd, sb[4*j4+2]), 0.f), wrow[4*j4+2], partial);
        partial = fmaf(fmaxf(fmaf(a.w, nd, sb[4*j4+3]), 0.f), wrow[4*j4+3], partial);
    }

    // groups of 4 lanes are warp-aligned (blockDim % 4 == 0, N % 4 == 0)
    partial += __shfl_xor_sync(0xFFFFFFFFu, partial, 1);
    partial += __shfl_xor_sync(0xFFFFFFFFu, partial, 2);
    if (k == 0) out[n >> 2] = partial + __ldg(bd);
}

// ---------------------------------------------------------------------------
extern "C" void kernel_launch(void* const* d_in, const int* in_sizes, int n_in,
                              void* d_out, int out_size) {
    const float* feats = (const float*)d_in[0];
    const int*   src   = (const int*)  d_in[1];
    const int*   dst   = (const int*)  d_in[2];
    const float* W1    = (const float*)d_in[3];
    const float* b1    = (const float*)d_in[4];
    const float* W2    = (const float*)d_in[5];
    const float* b2    = (const float*)d_in[6];
    const float* Wd    = (const float*)d_in[7];
    const float* bd    = (const float*)d_in[8];
    float* out = (float*)d_out;

    const int T = 256;
    int gN = (N_NODES + T - 1) / T;
    int gE = (N_EDGES + T - 1) / T;
    unsigned scatter_items = (unsigned)N_EDGES * 6u;
    int gS = (int)((scatter_items + T - 1) / T);

    k_zero<<<1024, T>>>();
    k_count<<<gE, T>>>(src, dst);
    k_norm<<<gN, T>>>();
    k_transform1<<<gN, T>>>(feats, W1);
    k_scatter<<<gS, T>>>(src, dst);
    k_mid<<<gN, T>>>(W2, b1);
    k_scatter<<<gS, T>>>(src, dst);
    k_final<<<gN, T>>>(b2, Wd, bd, out);
}

// round 2
// speedup vs baseline: 1.0245x; 1.0245x over previous
#include <cuda_runtime.h>

#define N_NODES 200000
#define N_EDGES 1600000
#define F_IN    32
#define HDIM    24

// Scratch (allocation-free: device globals)
__device__ float g_x[N_NODES * HDIM];     // transformed features (input to scatter)
__device__ float g_agg[N_NODES * HDIM];   // scatter-add accumulator
__device__ int   g_deg_out[N_NODES];
__device__ int   g_deg_in[N_NODES];

// Weights in constant memory -> LDCU (uniform-const port), not LDS
__constant__ float cW1[F_IN * HDIM];
__constant__ float cW2[HDIM * HDIM];
__constant__ float cWd[4 * HDIM];
__constant__ float cb1[HDIM];
__constant__ float cb2[HDIM];
__constant__ float cbd[1];

// ---------------------------------------------------------------------------
// Degree count: 4 edges per thread via int4
__global__ void k_count(const int* __restrict__ src, const int* __restrict__ dst) {
    int i = blockIdx.x * blockDim.x + threadIdx.x;
    if (i >= N_EDGES / 4) return;
    int4 s = __ldg(reinterpret_cast<const int4*>(src) + i);
    int4 d = __ldg(reinterpret_cast<const int4*>(dst) + i);
    atomicAdd(&g_deg_out[s.x], 1);
    atomicAdd(&g_deg_out[s.y], 1);
    atomicAdd(&g_deg_out[s.z], 1);
    atomicAdd(&g_deg_out[s.w], 1);
    atomicAdd(&g_deg_in[d.x], 1);
    atomicAdd(&g_deg_in[d.y], 1);
    atomicAdd(&g_deg_in[d.z], 1);
    atomicAdd(&g_deg_in[d.w], 1);
}

// x = ns * (features @ W1)   [ns factored out of the inner product]
__global__ void __launch_bounds__(256) k_transform1(const float* __restrict__ feats) {
    int n = blockIdx.x * blockDim.x + threadIdx.x;
    if (n >= N_NODES) return;

    // Stage all 8 loads first -> MLP 8
    const float4* frow = reinterpret_cast<const float4*>(feats + (size_t)n * F_IN);
    float4 f[8];
#pragma unroll
    for (int i = 0; i < 8; i++) f[i] = __ldg(frow + i);

    float ns = rsqrtf(fmaxf((float)g_deg_out[n], 1.0f));

    float acc[HDIM];
#pragma unroll
    for (int j = 0; j < HDIM; j++) acc[j] = 0.0f;

    const float* fv = reinterpret_cast<const float*>(f);
#pragma unroll
    for (int k = 0; k < F_IN; k++) {
        float x = fv[k];
#pragma unroll
        for (int j = 0; j < HDIM; j++) acc[j] = fmaf(x, cW1[k * HDIM + j], acc[j]);
    }

    float4* orow = reinterpret_cast<float4*>(g_x + (size_t)n * HDIM);
#pragma unroll
    for (int j4 = 0; j4 < HDIM / 4; j4++)
        orow[j4] = make_float4(acc[4*j4] * ns, acc[4*j4+1] * ns,
                               acc[4*j4+2] * ns, acc[4*j4+3] * ns);
}

// agg[dst] += x[src], vectorized red.global.add.v4.f32 (6 work items per edge)
__global__ void k_scatter(const int* __restrict__ src, const int* __restrict__ dst) {
    unsigned tid = blockIdx.x * blockDim.x + threadIdx.x;
    if (tid >= (unsigned)N_EDGES * 6u) return;
    unsigned e = tid / 6u;
    unsigned j = tid - e * 6u;
    int s = __ldg(src + e);
    int d = __ldg(dst + e);
    float4 v = __ldg(reinterpret_cast<const float4*>(g_x) + ((unsigned)s * 6u + j));
    float* p = g_agg + ((unsigned)d * 6u + j) * 4u;
    asm volatile("red.global.add.v4.f32 [%0], {%1,%2,%3,%4};"
                 :: "l"(p), "f"(v.x), "f"(v.y), "f"(v.z), "f"(v.w)
                 : "memory");
}

// h = relu(agg*nd + b1); x = ns * (h @ W2); agg = 0 (fused re-zero)
__global__ void __launch_bounds__(256) k_mid() {
    int n = blockIdx.x * blockDim.x + threadIdx.x;
    if (n >= N_NODES) return;

    float4* arow = reinterpret_cast<float4*>(g_agg + (size_t)n * HDIM);
    float4 a[6];
#pragma unroll
    for (int i = 0; i < 6; i++) a[i] = arow[i];

    float nd = rsqrtf(fmaxf((float)g_deg_in[n], 1.0f));
    float ns = rsqrtf(fmaxf((float)g_deg_out[n], 1.0f));

    float h[HDIM];
    const float* av = reinterpret_cast<const float*>(a);
#pragma unroll
    for (int j = 0; j < HDIM; j++)
        h[j] = fmaxf(fmaf(av[j], nd, cb1[j]), 0.0f);

#pragma unroll
    for (int i = 0; i < 6; i++) arow[i] = make_float4(0.f, 0.f, 0.f, 0.f);

    float acc[HDIM];
#pragma unroll
    for (int j = 0; j < HDIM; j++) acc[j] = 0.0f;
#pragma unroll
    for (int k = 0; k < HDIM; k++) {
#pragma unroll
        for (int j = 0; j < HDIM; j++) acc[j] = fmaf(h[k], cW2[k * HDIM + j], acc[j]);
    }

    float4* orow = reinterpret_cast<float4*>(g_x + (size_t)n * HDIM);
#pragma unroll
    for (int j4 = 0; j4 < HDIM / 4; j4++)
        orow[j4] = make_float4(acc[4*j4] * ns, acc[4*j4+1] * ns,
                               acc[4*j4+2] * ns, acc[4*j4+3] * ns);
}

// h2 = relu(agg*nd + b2); out[g] = sum over group-of-4 nodes of h2 . Wd_row + bd
__global__ void __launch_bounds__(256) k_final(float* __restrict__ out) {
    int n = blockIdx.x * blockDim.x + threadIdx.x;
    if (n >= N_NODES) return;

    const float4* arow = reinterpret_cast<const float4*>(g_agg + (size_t)n * HDIM);
    float4 a[6];
#pragma unroll
    for (int i = 0; i < 6; i++) a[i] = __ldg(arow + i);

    float nd = rsqrtf(fmaxf((float)g_deg_in[n], 1.0f));
    int k = n & 3;

    float partial = 0.0f;
    const float* av = reinterpret_cast<const float*>(a);
#pragma unroll
    for (int j = 0; j < HDIM; j++)
        partial = fmaf(fmaxf(fmaf(av[j], nd, cb2[j]), 0.0f), cWd[k * HDIM + j], partial);

    // groups of 4 lanes are warp-aligned (blockDim % 4 == 0, N % 4 == 0)
    partial += __shfl_xor_sync(0xFFFFFFFFu, partial, 1);
    partial += __shfl_xor_sync(0xFFFFFFFFu, partial, 2);
    if (k == 0) out[n >> 2] = partial + cbd[0];
}

// ---------------------------------------------------------------------------
extern "C" void kernel_launch(void* const* d_in, const int* in_sizes, int n_in,
                              void* d_out, int out_size) {
    const float* feats = (const float*)d_in[0];
    const int*   src   = (const int*)  d_in[1];
    const int*   dst   = (const int*)  d_in[2];
    float* out = (float*)d_out;

    void *p_agg, *p_dout, *p_din;
    cudaGetSymbolAddress(&p_agg, g_agg);
    cudaGetSymbolAddress(&p_dout, g_deg_out);
    cudaGetSymbolAddress(&p_din, g_deg_in);

    cudaMemsetAsync(p_agg, 0, sizeof(float) * N_NODES * HDIM);
    cudaMemsetAsync(p_dout, 0, sizeof(int) * N_NODES);
    cudaMemsetAsync(p_din, 0, sizeof(int) * N_NODES);

    cudaMemcpyToSymbolAsync(cW1, d_in[3], sizeof(float) * F_IN * HDIM, 0, cudaMemcpyDeviceToDevice);
    cudaMemcpyToSymbolAsync(cb1, d_in[4], sizeof(float) * HDIM, 0, cudaMemcpyDeviceToDevice);
    cudaMemcpyToSymbolAsync(cW2, d_in[5], sizeof(float) * HDIM * HDIM, 0, cudaMemcpyDeviceToDevice);
    cudaMemcpyToSymbolAsync(cb2, d_in[6], sizeof(float) * HDIM, 0, cudaMemcpyDeviceToDevice);
    cudaMemcpyToSymbolAsync(cWd, d_in[7], sizeof(float) * 4 * HDIM, 0, cudaMemcpyDeviceToDevice);
    cudaMemcpyToSymbolAsync(cbd, d_in[8], sizeof(float), 0, cudaMemcpyDeviceToDevice);

    const int T = 256;
    int gN = (N_NODES + T - 1) / T;
    int gC = (N_EDGES / 4 + T - 1) / T;
    unsigned scatter_items = (unsigned)N_EDGES * 6u;
    int gS = (int)((scatter_items + T - 1) / T);

    k_count<<<gC, T>>>(src, dst);
    k_transform1<<<gN, T>>>(feats);
    k_scatter<<<gS, T>>>(src, dst);
    k_mid<<<gN, T>>>();
    k_scatter<<<gS, T>>>(src, dst);
    k_final<<<gN, T>>>(out);
}

// round 3
// speedup vs baseline: 1.1820x; 1.1537x over previous
#include <cuda_runtime.h>

#define N_NODES 200000
#define N_EDGES 1600000
#define F_IN    32
#define HDIM    24
#define NBLK    196            // ceil(N_NODES / 1024) scan blocks

// Scratch (allocation-free: device globals)
__device__ float g_x[N_NODES * HDIM];     // transformed features (gather source)
__device__ float g_agg[N_NODES * HDIM];   // aggregation result
__device__ int   g_deg_out[N_NODES];
__device__ int   g_deg_in[N_NODES];
__device__ int   g_row_ptr[N_NODES + 1];  // CSR by dst
__device__ int   g_cursor[N_NODES];
__device__ int   g_scan_tmp[N_NODES];
__device__ int   g_block_sum[NBLK];
__device__ int   g_block_off[NBLK];
__device__ int   g_csr_src[N_EDGES];

// Weights in constant memory
__constant__ float cW1[F_IN * HDIM];
__constant__ float cW2[HDIM * HDIM];
__constant__ float cWd[4 * HDIM];
__constant__ float cb1[HDIM];
__constant__ float cb2[HDIM];
__constant__ float cbd[1];

// ---------------------------------------------------------------------------
// Degree count: 4 edges per thread via int4
__global__ void k_count(const int* __restrict__ src, const int* __restrict__ dst) {
    int i = blockIdx.x * blockDim.x + threadIdx.x;
    if (i >= N_EDGES / 4) return;
    int4 s = __ldg(reinterpret_cast<const int4*>(src) + i);
    int4 d = __ldg(reinterpret_cast<const int4*>(dst) + i);
    atomicAdd(&g_deg_out[s.x], 1);
    atomicAdd(&g_deg_out[s.y], 1);
    atomicAdd(&g_deg_out[s.z], 1);
    atomicAdd(&g_deg_out[s.w], 1);
    atomicAdd(&g_deg_in[d.x], 1);
    atomicAdd(&g_deg_in[d.y], 1);
    atomicAdd(&g_deg_in[d.z], 1);
    atomicAdd(&g_deg_in[d.w], 1);
}

// ------------------- exclusive scan of deg_in -> row_ptr --------------------
__global__ void k_scanA() {                 // per-block scan, 1024 items/block
    __shared__ int sw[8];
    int tidx = threadIdx.x;
    int base = blockIdx.x * 1024 + tidx * 4;
    int d0 = 0, d1 = 0, d2 = 0, d3 = 0;
    if (base + 3 < N_NODES) {
        int4 d = *reinterpret_cast<const int4*>(&g_deg_in[base]);
        d0 = d.x; d1 = d.y; d2 = d.z; d3 = d.w;
    } else if (base < N_NODES) {
        d0 = g_deg_in[base];
        if (base + 1 < N_NODES) d1 = g_deg_in[base + 1];
        if (base + 2 < N_NODES) d2 = g_deg_in[base + 2];
    }
    int s0 = d0, s1 = s0 + d1, s2 = s1 + d2, s3 = s2 + d3;
    int lane = tidx & 31, wid = tidx >> 5;
    int v = s3;
#pragma unroll
    for (int o = 1; o < 32; o <<= 1) {
        int t = __shfl_up_sync(0xFFFFFFFFu, v, o);
        if (lane >= o) v += t;
    }
    if (lane == 31) sw[wid] = v;
    __syncthreads();
    if (wid == 0 && lane < 8) {
        int w = sw[lane];
#pragma unroll
        for (int o = 1; o < 8; o <<= 1) {
            int t = __shfl_up_sync(0xFFu, w, o);
            if (lane >= o) w += t;
        }
        sw[lane] = w;
    }
    __syncthreads();
    int excl = (wid > 0 ? sw[wid - 1] : 0) + (v - s3);  // exclusive prefix in block
    if (base < N_NODES) {
        g_scan_tmp[base] = excl;
        if (base + 1 < N_NODES) g_scan_tmp[base + 1] = excl + s0;
        if (base + 2 < N_NODES) g_scan_tmp[base + 2] = excl + s1;
        if (base + 3 < N_NODES) g_scan_tmp[base + 3] = excl + s2;
    }
    if (tidx == 255) g_block_sum[blockIdx.x] = excl + s3;
}

__global__ void k_scanB() {                 // single block scans block sums
    __shared__ int sw[8];
    int tid = threadIdx.x;
    int v0 = (tid < NBLK) ? g_block_sum[tid] : 0;
    int lane = tid & 31, wid = tid >> 5;
    int v = v0;
#pragma unroll
    for (int o = 1; o < 32; o <<= 1) {
        int t = __shfl_up_sync(0xFFFFFFFFu, v, o);
        if (lane >= o) v += t;
    }
    if (lane == 31) sw[wid] = v;
    __syncthreads();
    if (wid == 0 && lane < 8) {
        int w = sw[lane];
#pragma unroll
        for (int o = 1; o < 8; o <<= 1) {
            int t = __shfl_up_sync(0xFFu, w, o);
            if (lane >= o) w += t;
        }
        sw[lane] = w;
    }
    __syncthreads();
    int excl = (wid > 0 ? sw[wid - 1] : 0) + (v - v0);
    if (tid < NBLK) g_block_off[tid] = excl;
    if (tid == 0) g_row_ptr[N_NODES] = N_EDGES;
}

__global__ void k_scanC() {                 // add block offsets, init cursors
    int base = blockIdx.x * 1024 + threadIdx.x * 4;
    int off = g_block_off[blockIdx.x];
#pragma unroll
    for (int q = 0; q < 4; q++) {
        int i = base + q;
        if (i < N_NODES) {
            int r = g_scan_tmp[i] + off;
            g_row_ptr[i] = r;
            g_cursor[i] = r;
        }
    }
}

// CSR fill: place src of each edge into its dst bucket
__global__ void k_fill(const int* __restrict__ src, const int* __restrict__ dst) {
    int i = blockIdx.x * blockDim.x + threadIdx.x;
    if (i >= N_EDGES / 4) return;
    int4 s = __ldg(reinterpret_cast<const int4*>(src) + i);
    int4 d = __ldg(reinterpret_cast<const int4*>(dst) + i);
    g_csr_src[atomicAdd(&g_cursor[d.x], 1)] = s.x;
    g_csr_src[atomicAdd(&g_cursor[d.y], 1)] = s.y;
    g_csr_src[atomicAdd(&g_cursor[d.z], 1)] = s.z;
    g_csr_src[atomicAdd(&g_cursor[d.w], 1)] = s.w;
}

// ---------------------------------------------------------------------------
// x = ns * (features @ W1)
__global__ void __launch_bounds__(256) k_transform1(const float* __restrict__ feats) {
    int n = blockIdx.x * blockDim.x + threadIdx.x;
    if (n >= N_NODES) return;

    const float4* frow = reinterpret_cast<const float4*>(feats + (size_t)n * F_IN);
    float4 f[8];
#pragma unroll
    for (int i = 0; i < 8; i++) f[i] = __ldg(frow + i);

    float ns = rsqrtf(fmaxf((float)g_deg_out[n], 1.0f));

    float acc[HDIM];
#pragma unroll
    for (int j = 0; j < HDIM; j++) acc[j] = 0.0f;

    const float* fv = reinterpret_cast<const float*>(f);
#pragma unroll
    for (int k = 0; k < F_IN; k++) {
        float x = fv[k];
#pragma unroll
        for (int j = 0; j < HDIM; j++) acc[j] = fmaf(x, cW1[k * HDIM + j], acc[j]);
    }

    float4* orow = reinterpret_cast<float4*>(g_x + (size_t)n * HDIM);
#pragma unroll
    for (int j4 = 0; j4 < HDIM / 4; j4++)
        orow[j4] = make_float4(acc[4*j4] * ns, acc[4*j4+1] * ns,
                               acc[4*j4+2] * ns, acc[4*j4+3] * ns);
}

// Pull-mode aggregation: agg[n] = sum_{e in in(n)} x[src[e]]
// 6 threads per node, one float4 chunk each. Atomic-free.
__global__ void __launch_bounds__(192) k_gather() {
    int t = blockIdx.x * 192 + threadIdx.x;
    int node = t / 6;
    int j = t - node * 6;
    if (node >= N_NODES) return;

    int beg = __ldg(&g_row_ptr[node]);
    int end = __ldg(&g_row_ptr[node + 1]);

    const float4* x4 = reinterpret_cast<const float4*>(g_x);
    float4 acc = make_float4(0.f, 0.f, 0.f, 0.f);

    int e = beg;
    for (; e + 1 < end; e += 2) {           // 2x unroll -> MLP
        int s0 = __ldg(&g_csr_src[e]);
        int s1 = __ldg(&g_csr_src[e + 1]);
        float4 v0 = __ldg(x4 + (size_t)s0 * 6 + j);
        float4 v1 = __ldg(x4 + (size_t)s1 * 6 + j);
        acc.x += v0.x + v1.x;
        acc.y += v0.y + v1.y;
        acc.z += v0.z + v1.z;
        acc.w += v0.w + v1.w;
    }
    if (e < end) {
        int s = __ldg(&g_csr_src[e]);
        float4 v = __ldg(x4 + (size_t)s * 6 + j);
        acc.x += v.x; acc.y += v.y; acc.z += v.z; acc.w += v.w;
    }

    reinterpret_cast<float4*>(g_agg)[(size_t)node * 6 + j] = acc;
}

// h = relu(agg*nd + b1); x = ns * (h @ W2)
__global__ void __launch_bounds__(256) k_mid() {
    int n = blockIdx.x * blockDim.x + threadIdx.x;
    if (n >= N_NODES) return;

    const float4* arow = reinterpret_cast<const float4*>(g_agg + (size_t)n * HDIM);
    float4 a[6];
#pragma unroll
    for (int i = 0; i < 6; i++) a[i] = __ldg(arow + i);

    float nd = rsqrtf(fmaxf((float)g_deg_in[n], 1.0f));
    float ns = rsqrtf(fmaxf((float)g_deg_out[n], 1.0f));

    float h[HDIM];
    const float* av = reinterpret_cast<const float*>(a);
#pragma unroll
    for (int j = 0; j < HDIM; j++)
        h[j] = fmaxf(fmaf(av[j], nd, cb1[j]), 0.0f);

    float acc[HDIM];
#pragma unroll
    for (int j = 0; j < HDIM; j++) acc[j] = 0.0f;
#pragma unroll
    for (int k = 0; k < HDIM; k++) {
#pragma unroll
        for (int j = 0; j < HDIM; j++) acc[j] = fmaf(h[k], cW2[k * HDIM + j], acc[j]);
    }

    float4* orow = reinterpret_cast<float4*>(g_x + (size_t)n * HDIM);
#pragma unroll
    for (int j4 = 0; j4 < HDIM / 4; j4++)
        orow[j4] = make_float4(acc[4*j4] * ns, acc[4*j4+1] * ns,
                               acc[4*j4+2] * ns, acc[4*j4+3] * ns);
}

// h2 = relu(agg*nd + b2); grouped readout with 4-lane butterfly reduce
__global__ void __launch_bounds__(256) k_final(float* __restrict__ out) {
    int n = blockIdx.x * blockDim.x + threadIdx.x;
    if (n >= N_NODES) return;

    const float4* arow = reinterpret_cast<const float4*>(g_agg + (size_t)n * HDIM);
    float4 a[6];
#pragma unroll
    for (int i = 0; i < 6; i++) a[i] = __ldg(arow + i);

    float nd = rsqrtf(fmaxf((float)g_deg_in[n], 1.0f));
    int k = n & 3;

    float partial = 0.0f;
    const float* av = reinterpret_cast<const float*>(a);
#pragma unroll
    for (int j = 0; j < HDIM; j++)
        partial = fmaf(fmaxf(fmaf(av[j], nd, cb2[j]), 0.0f), cWd[k * HDIM + j], partial);

    partial += __shfl_xor_sync(0xFFFFFFFFu, partial, 1);
    partial += __shfl_xor_sync(0xFFFFFFFFu, partial, 2);
    if (k == 0) out[n >> 2] = partial + cbd[0];
}

// ---------------------------------------------------------------------------
extern "C" void kernel_launch(void* const* d_in, const int* in_sizes, int n_in,
                              void* d_out, int out_size) {
    const float* feats = (const float*)d_in[0];
    const int*   src   = (const int*)  d_in[1];
    const int*   dst   = (const int*)  d_in[2];
    float* out = (float*)d_out;

    void *p_dout, *p_din;
    cudaGetSymbolAddress(&p_dout, g_deg_out);
    cudaGetSymbolAddress(&p_din, g_deg_in);
    cudaMemsetAsync(p_dout, 0, sizeof(int) * N_NODES);
    cudaMemsetAsync(p_din, 0, sizeof(int) * N_NODES);

    cudaMemcpyToSymbolAsync(cW1, d_in[3], sizeof(float) * F_IN * HDIM, 0, cudaMemcpyDeviceToDevice);
    cudaMemcpyToSymbolAsync(cb1, d_in[4], sizeof(float) * HDIM, 0, cudaMemcpyDeviceToDevice);
    cudaMemcpyToSymbolAsync(cW2, d_in[5], sizeof(float) * HDIM * HDIM, 0, cudaMemcpyDeviceToDevice);
    cudaMemcpyToSymbolAsync(cb2, d_in[6], sizeof(float) * HDIM, 0, cudaMemcpyDeviceToDevice);
    cudaMemcpyToSymbolAsync(cWd, d_in[7], sizeof(float) * 4 * HDIM, 0, cudaMemcpyDeviceToDevice);
    cudaMemcpyToSymbolAsync(cbd, d_in[8], sizeof(float), 0, cudaMemcpyDeviceToDevice);

    const int T = 256;
    int gN = (N_NODES + T - 1) / T;
    int gC = (N_EDGES / 4 + T - 1) / T;
    int gG = (N_NODES * 6 + 191) / 192;

    k_count<<<gC, T>>>(src, dst);
    k_scanA<<<NBLK, 256>>>();
    k_scanB<<<1, 256>>>();
    k_scanC<<<NBLK, 256>>>();
    k_fill<<<gC, T>>>(src, dst);
    k_transform1<<<gN, T>>>(feats);
    k_gather<<<gG, 192>>>();
    k_mid<<<gN, T>>>();
    k_gather<<<gG, 192>>>();
    k_final<<<gN, T>>>(out);
}